// round 1
// baseline (speedup 1.0000x reference)
#include <cuda_runtime.h>

#define BB 128
#define TT 256
#define DD 64
#define HH 512
#define NBLK 128
#define NTHR 512
#define PRED_SZ (BB*(TT-1)*DD)

#define W1_F (576*16)
#define W2_F (1024*16)
#define TILE_F (64*129)
#define SMEM_FLOATS (W1_F + W2_F + 512 + 16 + 16 + 512 + 512 + 2*TILE_F)

__device__ float g_h1[2][BB*HH];
__device__ float g_h2[2][BB*HH];
__device__ float g_cur[BB*DD];
__device__ unsigned int g_bar;

__device__ __forceinline__ unsigned long long pack2(float x) {
    unsigned int u = __float_as_uint(x);
    unsigned long long r;
    asm("mov.b64 %0, {%1, %1};" : "=l"(r) : "r"(u));
    return r;
}
__device__ __forceinline__ void fma2(unsigned long long &d, unsigned long long a, unsigned long long b) {
    asm("fma.rn.f32x2 %0, %1, %2, %0;" : "+l"(d) : "l"(a), "l"(b));
}
__device__ __forceinline__ void unpack2(unsigned long long v, float &lo, float &hi) {
    unsigned int ulo, uhi;
    asm("mov.b64 {%0, %1}, %2;" : "=r"(ulo), "=r"(uhi) : "l"(v));
    lo = __uint_as_float(ulo); hi = __uint_as_float(uhi);
}

__device__ __forceinline__ void grid_barrier() {
    __syncthreads();
    if (threadIdx.x == 0) {
        __threadfence();
        unsigned my = atomicAdd(&g_bar, 1u) + 1u;
        unsigned target = my + (NBLK - 1u) - ((my - 1u) % NBLK);
        while ((int)(*(volatile unsigned*)&g_bar - target) < 0) __nanosleep(32);
        __threadfence();
    }
    __syncthreads();
}

// Stage a 64k x 128r chunk (global row-major, rowStride floats) into a
// transposed 129-padded tile: tile[k*129 + r].
__device__ __forceinline__ void stage_ldg(float4 pf[4], const float* __restrict__ src,
                                          int stride, int kofs, int tid) {
    #pragma unroll
    for (int q = 0; q < 4; q++) {
        int lin = q*NTHR + tid;
        int r = lin >> 4, kq = lin & 15;
        pf[q] = *(const float4*)(src + r*stride + kofs + kq*4);
    }
}
__device__ __forceinline__ void stage_sts(float* tile, const float4 pf[4], int tid) {
    #pragma unroll
    for (int q = 0; q < 4; q++) {
        int lin = q*NTHR + tid;
        int r = lin >> 4, kq = lin & 15;
        tile[(kq*4+0)*129 + r] = pf[q].x;
        tile[(kq*4+1)*129 + r] = pf[q].y;
        tile[(kq*4+2)*129 + r] = pf[q].z;
        tile[(kq*4+3)*129 + r] = pf[q].w;
    }
}

// One 64-K chunk, split 16 k's per thread-group; 16 output cols as 8 f32x2 accs.
__device__ __forceinline__ void compute_chunk(unsigned long long acc[8], const float* tile,
                                              const float* wk, int grp, int rr) {
    const float* tp = tile + (grp*16)*129 + rr;
    const float* wp = wk + (grp*16)*16;
    #pragma unroll
    for (int kk = 0; kk < 16; kk++) {
        unsigned long long hh = pack2(tp[kk*129]);
        const ulonglong2* wv = (const ulonglong2*)(wp + kk*16);
        ulonglong2 w01 = wv[0], w23 = wv[1], w45 = wv[2], w67 = wv[3];
        fma2(acc[0], hh, w01.x); fma2(acc[1], hh, w01.y);
        fma2(acc[2], hh, w23.x); fma2(acc[3], hh, w23.y);
        fma2(acc[4], hh, w45.x); fma2(acc[5], hh, w45.y);
        fma2(acc[6], hh, w67.x); fma2(acc[7], hh, w67.y);
    }
}

__global__ void __launch_bounds__(NTHR, 1) ajrnn_kernel(
    const float* __restrict__ x,
    const float* __restrict__ k0, const float* __restrict__ r0, const float* __restrict__ b0,
    const float* __restrict__ k1, const float* __restrict__ r1, const float* __restrict__ b1,
    const float* __restrict__ Wm, const float* __restrict__ bias,
    float* __restrict__ out)
{
    extern __shared__ float sm[];
    float* sh_w1 = sm;                       // [576][16]
    float* sh_w2 = sh_w1 + W1_F;             // [1024][16]
    float* sh_wp = sh_w2 + W2_F;             // [512] pred W column
    float* sh_b0 = sh_wp + 512;              // [16]
    float* sh_b1 = sh_b0 + 16;               // [16]
    float* sh_c1 = sh_b1 + 16;               // [128][4]
    float* sh_c2 = sh_c1 + 512;              // [128][4]
    float* sh_tile = sh_c2 + 512;            // 2 x TILE_F
    float* sh_red  = sh_tile;                // alias (used after syncthreads)

    const int tid = threadIdx.x;
    const int bid = blockIdx.x;
    const int n0  = bid * 4;                 // 4 hidden units per layer per block
    const int dcol = bid >> 1;               // pred column handled by this block
    const int grp = tid >> 7;                // K-group 0..3
    const int rr  = tid & 127;               // row 0..127
    float* tA = sh_tile;
    float* tB = sh_tile + TILE_F;

    // ---------------- init ----------------
    for (int idx = tid; idx < W1_F; idx += NTHR) {
        int k = idx >> 4, c = idx & 15;
        int col = (c & 3) * HH + n0 + (c >> 2);       // gate-major cols, c = j*4+g
        sh_w1[idx] = (k < DD) ? k0[k*2048 + col] : r0[(k-DD)*2048 + col];
    }
    for (int idx = tid; idx < W2_F; idx += NTHR) {
        int k = idx >> 4, c = idx & 15;
        int col = (c & 3) * HH + n0 + (c >> 2);
        sh_w2[idx] = (k < HH) ? k1[k*2048 + col] : r1[(k-HH)*2048 + col];
    }
    sh_wp[tid] = Wm[tid*DD + dcol];                   // tid covers 0..511
    if (tid < 16) {
        int col = (tid & 3) * HH + n0 + (tid >> 2);
        sh_b0[tid] = b0[col];
        sh_b1[tid] = b1[col];
    }
    sh_c1[tid] = 0.f;
    sh_c2[tid] = 0.f;
    g_h1[0][bid*HH + tid] = 0.f;
    g_h2[0][bid*HH + tid] = 0.f;
    const float biasd = bias[dcol];
    grid_barrier();

    // ---------------- time loop ----------------
    for (int t = 0; t < TT; t++) {
        const int rb = t & 1;      // read buffer parity
        const int wb = rb ^ 1;     // write buffer parity

        // ---- Phase A: pred (output!) + imputed cur ----
        {
            const int r  = ((bid & 1) * 64) + (tid >> 3);
            const int l8 = tid & 7;
            if (t == 0) {
                if (l8 == 0) g_cur[r*DD + dcol] = x[(r*TT)*DD + dcol];
            } else {
                const float* hrow = &g_h2[rb][r*HH + l8*64];
                const float* wv = sh_wp + l8*64;
                float s = 0.f;
                #pragma unroll
                for (int kk = 0; kk < 64; kk += 4) {
                    float4 h4 = *(const float4*)(hrow + kk);
                    s += h4.x*wv[kk] + h4.y*wv[kk+1] + h4.z*wv[kk+2] + h4.w*wv[kk+3];
                }
                s += __shfl_xor_sync(0xffffffffu, s, 4);
                s += __shfl_xor_sync(0xffffffffu, s, 2);
                s += __shfl_xor_sync(0xffffffffu, s, 1);
                if (l8 == 0) {
                    float p  = s + biasd;
                    float xv = x[(r*TT + t)*DD + dcol];
                    g_cur[r*DD + dcol] = (xv == 128.0f) ? p : xv;
                    out[(r*(TT-1) + (t-1))*DD + dcol] = p;   // prediction output row
                }
            }
        }
        grid_barrier();

        // ---- Phase B: layer-1 z = [cur | h1_old] @ W1 -> gates -> h1_new ----
        {
            unsigned long long acc[8] = {0,0,0,0,0,0,0,0};
            float4 pf[4];
            stage_ldg(pf, g_cur, DD, 0, tid);            // chunk 0 = cur (K=64)
            stage_sts(tA, pf, tid);
            __syncthreads();
            #pragma unroll 1
            for (int c = 0; c < 9; c++) {
                if (c + 1 < 9) stage_ldg(pf, g_h1[rb], HH, c*64, tid);  // chunks 1..8 = h1_old
                compute_chunk(acc, (c & 1) ? tB : tA, sh_w1 + c*64*16, grp, rr);
                if (c + 1 < 9) stage_sts((c & 1) ? tA : tB, pf, tid);
                __syncthreads();
            }
            float* my = sh_red + (grp*128 + rr)*16;
            #pragma unroll
            for (int p2 = 0; p2 < 8; p2++) { float lo, hi; unpack2(acc[p2], lo, hi); my[2*p2] = lo; my[2*p2+1] = hi; }
            __syncthreads();
            if (tid < 128) {
                const int r = tid;
                float hnew[4];
                #pragma unroll
                for (int j = 0; j < 4; j++) {
                    float z[4];
                    #pragma unroll
                    for (int g = 0; g < 4; g++) {
                        int c16 = j*4 + g;
                        z[g] = sh_red[(0*128+r)*16 + c16] + sh_red[(1*128+r)*16 + c16]
                             + sh_red[(2*128+r)*16 + c16] + sh_red[(3*128+r)*16 + c16] + sh_b0[c16];
                    }
                    float ig = 1.f/(1.f + expf(-z[0]));
                    float fg = 1.f/(1.f + expf(-z[1]));
                    float gg = tanhf(z[2]);
                    float og = 1.f/(1.f + expf(-z[3]));
                    float cn = fg*sh_c1[r*4+j] + ig*gg;
                    sh_c1[r*4+j] = cn;
                    hnew[j] = og*tanhf(cn);
                }
                *(float4*)&g_h1[wb][r*HH + n0] = make_float4(hnew[0], hnew[1], hnew[2], hnew[3]);
            }
        }
        grid_barrier();

        // ---- Phase C: layer-2 z = [h1_new | h2_old] @ W2 -> gates -> h2_new ----
        {
            unsigned long long acc[8] = {0,0,0,0,0,0,0,0};
            float4 pf[4];
            stage_ldg(pf, g_h1[wb], HH, 0, tid);
            stage_sts(tA, pf, tid);
            __syncthreads();
            #pragma unroll 1
            for (int c = 0; c < 16; c++) {
                if (c + 1 < 16) {
                    const float* src = (c + 1 < 8) ? g_h1[wb] : g_h2[rb];
                    int kofs = (c + 1 < 8) ? (c+1)*64 : (c+1-8)*64;
                    stage_ldg(pf, src, HH, kofs, tid);
                }
                compute_chunk(acc, (c & 1) ? tB : tA, sh_w2 + c*64*16, grp, rr);
                if (c + 1 < 16) stage_sts((c & 1) ? tA : tB, pf, tid);
                __syncthreads();
            }
            float* my = sh_red + (grp*128 + rr)*16;
            #pragma unroll
            for (int p2 = 0; p2 < 8; p2++) { float lo, hi; unpack2(acc[p2], lo, hi); my[2*p2] = lo; my[2*p2+1] = hi; }
            __syncthreads();
            if (tid < 128) {
                const int r = tid;
                float hnew[4];
                #pragma unroll
                for (int j = 0; j < 4; j++) {
                    float z[4];
                    #pragma unroll
                    for (int g = 0; g < 4; g++) {
                        int c16 = j*4 + g;
                        z[g] = sh_red[(0*128+r)*16 + c16] + sh_red[(1*128+r)*16 + c16]
                             + sh_red[(2*128+r)*16 + c16] + sh_red[(3*128+r)*16 + c16] + sh_b1[c16];
                    }
                    float ig = 1.f/(1.f + expf(-z[0]));
                    float fg = 1.f/(1.f + expf(-z[1]));
                    float gg = tanhf(z[2]);
                    float og = 1.f/(1.f + expf(-z[3]));
                    float cn = fg*sh_c2[r*4+j] + ig*gg;
                    sh_c2[r*4+j] = cn;
                    hnew[j] = og*tanhf(cn);
                }
                *(float4*)&g_h2[wb][r*HH + n0] = make_float4(hnew[0], hnew[1], hnew[2], hnew[3]);
                if (t == TT-1) {
                    *(float4*)&out[PRED_SZ + r*HH + n0] = make_float4(hnew[0], hnew[1], hnew[2], hnew[3]);
                }
            }
        }
        grid_barrier();
    }
}

extern "C" void kernel_launch(void* const* d_in, const int* in_sizes, int n_in,
                              void* d_out, int out_size) {
    (void)in_sizes; (void)n_in; (void)out_size;
    const float* x    = (const float*)d_in[0];
    const float* k0   = (const float*)d_in[1];
    const float* r0   = (const float*)d_in[2];
    const float* b0   = (const float*)d_in[3];
    const float* k1   = (const float*)d_in[4];
    const float* r1   = (const float*)d_in[5];
    const float* b1   = (const float*)d_in[6];
    const float* Wm   = (const float*)d_in[7];
    const float* bias = (const float*)d_in[8];
    size_t smem = SMEM_FLOATS * sizeof(float);
    cudaFuncSetAttribute(ajrnn_kernel, cudaFuncAttributeMaxDynamicSharedMemorySize, (int)smem);
    ajrnn_kernel<<<NBLK, NTHR, smem>>>(x, k0, r0, b0, k1, r1, b1, Wm, bias, (float*)d_out);
}

// round 2
// speedup vs baseline: 1.2632x; 1.2632x over previous
#include <cuda_runtime.h>

#define BB 128
#define TT 256
#define DD 64
#define HH 512
#define NBLK 128
#define NTHR 512
#define PRED_SZ (BB*(TT-1)*DD)

#define W1_F (576*16)
#define W2_F (1024*16)
#define TILE_STRIDE 130
#define TILE_F (64*TILE_STRIDE)          // 8320 floats per tile
#define RED_STRIDE 17
#define RED_F (8*128*RED_STRIDE)         // 17408 floats
#define UNION_F (RED_F)                  // RED_F > 2*TILE_F? 17408 vs 16640 -> 17408
#define SMEM_FLOATS (W1_F + W2_F + 512 + 16 + 16 + 512 + 512 + UNION_F)

__device__ float g_h1[2][BB*HH];
__device__ float g_h2[2][BB*HH];
__device__ float g_cur[BB*DD];
__device__ unsigned int g_bar;

__device__ __forceinline__ unsigned long long pack2(float x) {
    unsigned int u = __float_as_uint(x);
    unsigned long long r;
    asm("mov.b64 %0, {%1, %1};" : "=l"(r) : "r"(u));
    return r;
}
__device__ __forceinline__ void fma2(unsigned long long &d, unsigned long long a, unsigned long long b) {
    asm("fma.rn.f32x2 %0, %1, %2, %0;" : "+l"(d) : "l"(a), "l"(b));
}
__device__ __forceinline__ void unpack2(unsigned long long v, float &lo, float &hi) {
    unsigned int ulo, uhi;
    asm("mov.b64 {%0, %1}, %2;" : "=r"(ulo), "=r"(uhi) : "l"(v));
    lo = __uint_as_float(ulo); hi = __uint_as_float(uhi);
}

__device__ __forceinline__ void grid_barrier() {
    __syncthreads();
    if (threadIdx.x == 0) {
        __threadfence();
        unsigned my = atomicAdd(&g_bar, 1u) + 1u;
        unsigned target = my + (NBLK - 1u) - ((my - 1u) % NBLK);
        while ((int)(*(volatile unsigned*)&g_bar - target) < 0) __nanosleep(32);
        __threadfence();
    }
    __syncthreads();
}

// ---- staging: 64k x 128r chunk -> transposed swizzled tile tile[k*130 + (r ^ (k&16))]
// mapping per float4 unit: kq_lo = lin&7, r = (lin>>3)&127, kq_hi = (lin>>10)&1
// LDG: 8 lanes cover one 128B line (coalesced). STS: conflict-free (proven via r^ (k&16) swizzle).
__device__ __forceinline__ void stage_ldg(float4 pf[4], const float* __restrict__ src,
                                          int stride, int kofs, int tid) {
    #pragma unroll
    for (int q = 0; q < 4; q++) {
        int lin = q*NTHR + tid;
        int kq = ((lin >> 10) & 1) * 8 + (lin & 7);
        int r  = (lin >> 3) & 127;
        pf[q] = *(const float4*)(src + r*stride + kofs + kq*4);
    }
}
__device__ __forceinline__ void stage_sts(float* tile, const float4 pf[4], int tid) {
    #pragma unroll
    for (int q = 0; q < 4; q++) {
        int lin = q*NTHR + tid;
        int kq = ((lin >> 10) & 1) * 8 + (lin & 7);
        int r  = (lin >> 3) & 127;
        int k0 = kq*4;
        int m  = (k0 & 16);              // bit4 of k is constant across i=0..3
        int rs = r ^ m;
        tile[(k0+0)*TILE_STRIDE + rs] = pf[q].x;
        tile[(k0+1)*TILE_STRIDE + rs] = pf[q].y;
        tile[(k0+2)*TILE_STRIDE + rs] = pf[q].z;
        tile[(k0+3)*TILE_STRIDE + rs] = pf[q].w;
    }
}

// One 64-k chunk: thread (s, rp) handles k_local in [s*8, s*8+8), rows 2rp,2rp+1, 16 cols.
// acc[0..7]: row A cols (2j,2j+1); acc[8..15]: row B.
__device__ __forceinline__ void compute_chunk(unsigned long long acc[16], const float* tile,
                                              const float* wk, int s, int rp) {
    #pragma unroll
    for (int kk = 0; kk < 8; kk++) {
        int k = s*8 + kk;
        float2 h = *(const float2*)&tile[k*TILE_STRIDE + ((2*rp) ^ (k & 16))];
        unsigned long long hA = pack2(h.x);
        unsigned long long hB = pack2(h.y);
        const ulonglong2* wv = (const ulonglong2*)(wk + k*16);
        ulonglong2 w01 = wv[0], w23 = wv[1], w45 = wv[2], w67 = wv[3];
        fma2(acc[0], hA, w01.x); fma2(acc[1], hA, w01.y);
        fma2(acc[2], hA, w23.x); fma2(acc[3], hA, w23.y);
        fma2(acc[4], hA, w45.x); fma2(acc[5], hA, w45.y);
        fma2(acc[6], hA, w67.x); fma2(acc[7], hA, w67.y);
        fma2(acc[8],  hB, w01.x); fma2(acc[9],  hB, w01.y);
        fma2(acc[10], hB, w23.x); fma2(acc[11], hB, w23.y);
        fma2(acc[12], hB, w45.x); fma2(acc[13], hB, w45.y);
        fma2(acc[14], hB, w67.x); fma2(acc[15], hB, w67.y);
    }
}

__device__ __forceinline__ void write_partials(float* red, const unsigned long long acc[16],
                                               int s, int rp) {
    int rA = 2*rp, rB = 2*rp + 1;
    float* pA = red + s*(128*RED_STRIDE) + rA*RED_STRIDE;
    float* pB = red + s*(128*RED_STRIDE) + rB*RED_STRIDE;
    #pragma unroll
    for (int j = 0; j < 8; j++) {
        float lo, hi;
        unpack2(acc[j], lo, hi);     pA[2*j] = lo; pA[2*j+1] = hi;
        unpack2(acc[j+8], lo, hi);   pB[2*j] = lo; pB[2*j+1] = hi;
    }
}

__global__ void __launch_bounds__(NTHR, 1) ajrnn_kernel(
    const float* __restrict__ x,
    const float* __restrict__ k0, const float* __restrict__ r0, const float* __restrict__ b0,
    const float* __restrict__ k1, const float* __restrict__ r1, const float* __restrict__ b1,
    const float* __restrict__ Wm, const float* __restrict__ bias,
    float* __restrict__ out)
{
    extern __shared__ float sm[];
    float* sh_w1 = sm;                       // [576][16]
    float* sh_w2 = sh_w1 + W1_F;             // [1024][16]
    float* sh_wp = sh_w2 + W2_F;             // [512]
    float* sh_b0 = sh_wp + 512;              // [16]
    float* sh_b1 = sh_b0 + 16;               // [16]
    float* sh_c1 = sh_b1 + 16;               // [128*4] idx = tid
    float* sh_c2 = sh_c1 + 512;              // [128*4]
    float* sh_un = sh_c2 + 512;              // union: tiles (2x8320) / red (17408)
    float* tA = sh_un;
    float* tB = sh_un + TILE_F;
    float* sh_red = sh_un;

    const int tid = threadIdx.x;
    const int bid = blockIdx.x;
    const int n0  = bid * 4;
    const int dcol = bid >> 1;
    const int s  = tid >> 6;                 // K-split group 0..7
    const int rp = tid & 63;                 // row pair index 0..63

    // ---------------- init ----------------
    for (int idx = tid; idx < W1_F; idx += NTHR) {
        int k = idx >> 4, c = idx & 15;
        int col = (c & 3) * HH + n0 + (c >> 2);
        sh_w1[idx] = (k < DD) ? k0[k*2048 + col] : r0[(k-DD)*2048 + col];
    }
    for (int idx = tid; idx < W2_F; idx += NTHR) {
        int k = idx >> 4, c = idx & 15;
        int col = (c & 3) * HH + n0 + (c >> 2);
        sh_w2[idx] = (k < HH) ? k1[k*2048 + col] : r1[(k-HH)*2048 + col];
    }
    sh_wp[tid] = Wm[tid*DD + dcol];
    if (tid < 16) {
        int col = (tid & 3) * HH + n0 + (tid >> 2);
        sh_b0[tid] = b0[col];
        sh_b1[tid] = b1[col];
    }
    sh_c1[tid] = 0.f;
    sh_c2[tid] = 0.f;
    g_h1[0][bid*HH + tid] = 0.f;
    g_h2[0][bid*HH + tid] = 0.f;
    const float biasd = bias[dcol];
    grid_barrier();

    // ---------------- time loop ----------------
    for (int t = 0; t < TT; t++) {
        const int rb = t & 1;
        const int wb = rb ^ 1;

        // ---- Phase A: pred (-> output) + imputed cur ----
        {
            const int r  = ((bid & 1) * 64) + (tid >> 3);
            const int l8 = tid & 7;
            if (t == 0) {
                if (l8 == 0) g_cur[r*DD + dcol] = x[(r*TT)*DD + dcol];
            } else {
                const float* hrow = &g_h2[rb][r*HH + l8*64];
                const float* wv = sh_wp + l8*64;
                float sacc = 0.f;
                #pragma unroll
                for (int kk = 0; kk < 64; kk += 4) {
                    float4 h4 = *(const float4*)(hrow + kk);
                    sacc += h4.x*wv[kk] + h4.y*wv[kk+1] + h4.z*wv[kk+2] + h4.w*wv[kk+3];
                }
                sacc += __shfl_xor_sync(0xffffffffu, sacc, 4);
                sacc += __shfl_xor_sync(0xffffffffu, sacc, 2);
                sacc += __shfl_xor_sync(0xffffffffu, sacc, 1);
                if (l8 == 0) {
                    float p  = sacc + biasd;
                    float xv = x[(r*TT + t)*DD + dcol];
                    g_cur[r*DD + dcol] = (xv == 128.0f) ? p : xv;
                    out[(r*(TT-1) + (t-1))*DD + dcol] = p;
                }
            }
        }
        grid_barrier();

        // ---- Phase B: z = [cur | h1_old] @ W1 -> gates -> h1_new ----
        {
            unsigned long long acc[16] = {0,0,0,0,0,0,0,0,0,0,0,0,0,0,0,0};
            float4 pf[4];
            stage_ldg(pf, g_cur, DD, 0, tid);
            stage_sts(tA, pf, tid);
            __syncthreads();
            #pragma unroll 1
            for (int c = 0; c < 9; c++) {
                if (c + 1 < 9) stage_ldg(pf, g_h1[rb], HH, c*64, tid);
                compute_chunk(acc, (c & 1) ? tB : tA, sh_w1 + c*64*16, s, rp);
                if (c + 1 < 9) stage_sts((c & 1) ? tA : tB, pf, tid);
                __syncthreads();
            }
            write_partials(sh_red, acc, s, rp);
            __syncthreads();
            {
                const int r = tid >> 2, j = tid & 3;
                float z[4];
                #pragma unroll
                for (int g = 0; g < 4; g++) {
                    int c16 = j*4 + g;
                    float sum = sh_b0[c16];
                    #pragma unroll
                    for (int ss = 0; ss < 8; ss++)
                        sum += sh_red[ss*(128*RED_STRIDE) + r*RED_STRIDE + c16];
                    z[g] = sum;
                }
                float ig = 1.f/(1.f + expf(-z[0]));
                float fg = 1.f/(1.f + expf(-z[1]));
                float gg = tanhf(z[2]);
                float og = 1.f/(1.f + expf(-z[3]));
                float cn = fg*sh_c1[tid] + ig*gg;
                sh_c1[tid] = cn;
                g_h1[wb][r*HH + n0 + j] = og*tanhf(cn);
            }
        }
        grid_barrier();

        // ---- Phase C: z = [h1_new | h2_old] @ W2 -> gates -> h2_new ----
        {
            unsigned long long acc[16] = {0,0,0,0,0,0,0,0,0,0,0,0,0,0,0,0};
            float4 pf[4];
            stage_ldg(pf, g_h1[wb], HH, 0, tid);
            stage_sts(tA, pf, tid);
            __syncthreads();
            #pragma unroll 1
            for (int c = 0; c < 16; c++) {
                if (c + 1 < 16) {
                    const float* src = (c + 1 < 8) ? g_h1[wb] : g_h2[rb];
                    int kofs = (c + 1 < 8) ? (c+1)*64 : (c+1-8)*64;
                    stage_ldg(pf, src, HH, kofs, tid);
                }
                compute_chunk(acc, (c & 1) ? tB : tA, sh_w2 + c*64*16, s, rp);
                if (c + 1 < 16) stage_sts((c & 1) ? tA : tB, pf, tid);
                __syncthreads();
            }
            write_partials(sh_red, acc, s, rp);
            __syncthreads();
            {
                const int r = tid >> 2, j = tid & 3;
                float z[4];
                #pragma unroll
                for (int g = 0; g < 4; g++) {
                    int c16 = j*4 + g;
                    float sum = sh_b1[c16];
                    #pragma unroll
                    for (int ss = 0; ss < 8; ss++)
                        sum += sh_red[ss*(128*RED_STRIDE) + r*RED_STRIDE + c16];
                    z[g] = sum;
                }
                float ig = 1.f/(1.f + expf(-z[0]));
                float fg = 1.f/(1.f + expf(-z[1]));
                float gg = tanhf(z[2]);
                float og = 1.f/(1.f + expf(-z[3]));
                float cn = fg*sh_c2[tid] + ig*gg;
                sh_c2[tid] = cn;
                float hn = og*tanhf(cn);
                g_h2[wb][r*HH + n0 + j] = hn;
                if (t == TT-1) out[PRED_SZ + r*HH + n0 + j] = hn;
            }
        }
        grid_barrier();
    }
}

extern "C" void kernel_launch(void* const* d_in, const int* in_sizes, int n_in,
                              void* d_out, int out_size) {
    (void)in_sizes; (void)n_in; (void)out_size;
    const float* x    = (const float*)d_in[0];
    const float* k0   = (const float*)d_in[1];
    const float* r0   = (const float*)d_in[2];
    const float* b0   = (const float*)d_in[3];
    const float* k1   = (const float*)d_in[4];
    const float* r1   = (const float*)d_in[5];
    const float* b1   = (const float*)d_in[6];
    const float* Wm   = (const float*)d_in[7];
    const float* bias = (const float*)d_in[8];
    size_t smem = SMEM_FLOATS * sizeof(float);
    cudaFuncSetAttribute(ajrnn_kernel, cudaFuncAttributeMaxDynamicSharedMemorySize, (int)smem);
    ajrnn_kernel<<<NBLK, NTHR, smem>>>(x, k0, r0, b0, k1, r1, b1, Wm, bias, (float*)d_out);
}

// round 3
// speedup vs baseline: 1.2652x; 1.0016x over previous
#include <cuda_runtime.h>

#define BB 128
#define TT 256
#define DD 64
#define HH 512
#define NBLK 128
#define NTHR 512
#define PRED_SZ (BB*(TT-1)*DD)

#define W1_F (576*16)
#define W2_F (1024*16)
#define TILE_STRIDE 130
#define TILE_F (64*TILE_STRIDE)          // 8320 floats per tile
#define RED_STRIDE 17
#define RED_F (8*128*RED_STRIDE)         // 17408 floats
#define UNION_F (RED_F)                  // RED_F > 2*TILE_F? 17408 vs 16640 -> 17408
#define SMEM_FLOATS (W1_F + W2_F + 512 + 16 + 16 + 512 + 512 + UNION_F)

__device__ float g_h1[2][BB*HH];
__device__ float g_h2[2][BB*HH];
__device__ float g_cur[BB*DD];
__device__ unsigned int g_bar;

__device__ __forceinline__ unsigned long long pack2(float x) {
    unsigned int u = __float_as_uint(x);
    unsigned long long r;
    asm("mov.b64 %0, {%1, %1};" : "=l"(r) : "r"(u));
    return r;
}
__device__ __forceinline__ void fma2(unsigned long long &d, unsigned long long a, unsigned long long b) {
    asm("fma.rn.f32x2 %0, %1, %2, %0;" : "+l"(d) : "l"(a), "l"(b));
}
__device__ __forceinline__ void unpack2(unsigned long long v, float &lo, float &hi) {
    unsigned int ulo, uhi;
    asm("mov.b64 {%0, %1}, %2;" : "=r"(ulo), "=r"(uhi) : "l"(v));
    lo = __uint_as_float(ulo); hi = __uint_as_float(uhi);
}

__device__ __forceinline__ void grid_barrier() {
    __syncthreads();
    if (threadIdx.x == 0) {
        __threadfence();
        unsigned my = atomicAdd(&g_bar, 1u) + 1u;
        unsigned target = my + (NBLK - 1u) - ((my - 1u) % NBLK);
        while ((int)(*(volatile unsigned*)&g_bar - target) < 0) __nanosleep(32);
        __threadfence();
    }
    __syncthreads();
}

// ---- staging: 64k x 128r chunk -> transposed swizzled tile tile[k*130 + (r ^ (k&16))]
// mapping per float4 unit: kq_lo = lin&7, r = (lin>>3)&127, kq_hi = (lin>>10)&1
// LDG: 8 lanes cover one 128B line (coalesced). STS: conflict-free (proven via r^ (k&16) swizzle).
__device__ __forceinline__ void stage_ldg(float4 pf[4], const float* __restrict__ src,
                                          int stride, int kofs, int tid) {
    #pragma unroll
    for (int q = 0; q < 4; q++) {
        int lin = q*NTHR + tid;
        int kq = ((lin >> 10) & 1) * 8 + (lin & 7);
        int r  = (lin >> 3) & 127;
        pf[q] = *(const float4*)(src + r*stride + kofs + kq*4);
    }
}
__device__ __forceinline__ void stage_sts(float* tile, const float4 pf[4], int tid) {
    #pragma unroll
    for (int q = 0; q < 4; q++) {
        int lin = q*NTHR + tid;
        int kq = ((lin >> 10) & 1) * 8 + (lin & 7);
        int r  = (lin >> 3) & 127;
        int k0 = kq*4;
        int m  = (k0 & 16);              // bit4 of k is constant across i=0..3
        int rs = r ^ m;
        tile[(k0+0)*TILE_STRIDE + rs] = pf[q].x;
        tile[(k0+1)*TILE_STRIDE + rs] = pf[q].y;
        tile[(k0+2)*TILE_STRIDE + rs] = pf[q].z;
        tile[(k0+3)*TILE_STRIDE + rs] = pf[q].w;
    }
}

// One 64-k chunk: thread (s, rp) handles k_local in [s*8, s*8+8), rows 2rp,2rp+1, 16 cols.
// acc[0..7]: row A cols (2j,2j+1); acc[8..15]: row B.
__device__ __forceinline__ void compute_chunk(unsigned long long acc[16], const float* tile,
                                              const float* wk, int s, int rp) {
    #pragma unroll
    for (int kk = 0; kk < 8; kk++) {
        int k = s*8 + kk;
        float2 h = *(const float2*)&tile[k*TILE_STRIDE + ((2*rp) ^ (k & 16))];
        unsigned long long hA = pack2(h.x);
        unsigned long long hB = pack2(h.y);
        const ulonglong2* wv = (const ulonglong2*)(wk + k*16);
        ulonglong2 w01 = wv[0], w23 = wv[1], w45 = wv[2], w67 = wv[3];
        fma2(acc[0], hA, w01.x); fma2(acc[1], hA, w01.y);
        fma2(acc[2], hA, w23.x); fma2(acc[3], hA, w23.y);
        fma2(acc[4], hA, w45.x); fma2(acc[5], hA, w45.y);
        fma2(acc[6], hA, w67.x); fma2(acc[7], hA, w67.y);
        fma2(acc[8],  hB, w01.x); fma2(acc[9],  hB, w01.y);
        fma2(acc[10], hB, w23.x); fma2(acc[11], hB, w23.y);
        fma2(acc[12], hB, w45.x); fma2(acc[13], hB, w45.y);
        fma2(acc[14], hB, w67.x); fma2(acc[15], hB, w67.y);
    }
}

__device__ __forceinline__ void write_partials(float* red, const unsigned long long acc[16],
                                               int s, int rp) {
    int rA = 2*rp, rB = 2*rp + 1;
    float* pA = red + s*(128*RED_STRIDE) + rA*RED_STRIDE;
    float* pB = red + s*(128*RED_STRIDE) + rB*RED_STRIDE;
    #pragma unroll
    for (int j = 0; j < 8; j++) {
        float lo, hi;
        unpack2(acc[j], lo, hi);     pA[2*j] = lo; pA[2*j+1] = hi;
        unpack2(acc[j+8], lo, hi);   pB[2*j] = lo; pB[2*j+1] = hi;
    }
}

__global__ void __launch_bounds__(NTHR, 1) ajrnn_kernel(
    const float* __restrict__ x,
    const float* __restrict__ k0, const float* __restrict__ r0, const float* __restrict__ b0,
    const float* __restrict__ k1, const float* __restrict__ r1, const float* __restrict__ b1,
    const float* __restrict__ Wm, const float* __restrict__ bias,
    float* __restrict__ out)
{
    extern __shared__ float sm[];
    float* sh_w1 = sm;                       // [576][16]
    float* sh_w2 = sh_w1 + W1_F;             // [1024][16]
    float* sh_wp = sh_w2 + W2_F;             // [512]
    float* sh_b0 = sh_wp + 512;              // [16]
    float* sh_b1 = sh_b0 + 16;               // [16]
    float* sh_c1 = sh_b1 + 16;               // [128*4] idx = tid
    float* sh_c2 = sh_c1 + 512;              // [128*4]
    float* sh_un = sh_c2 + 512;              // union: tiles (2x8320) / red (17408)
    float* tA = sh_un;
    float* tB = sh_un + TILE_F;
    float* sh_red = sh_un;

    const int tid = threadIdx.x;
    const int bid = blockIdx.x;
    const int n0  = bid * 4;
    const int dcol = bid >> 1;
    const int s  = tid >> 6;                 // K-split group 0..7
    const int rp = tid & 63;                 // row pair index 0..63

    // ---------------- init ----------------
    for (int idx = tid; idx < W1_F; idx += NTHR) {
        int k = idx >> 4, c = idx & 15;
        int col = (c & 3) * HH + n0 + (c >> 2);
        sh_w1[idx] = (k < DD) ? k0[k*2048 + col] : r0[(k-DD)*2048 + col];
    }
    for (int idx = tid; idx < W2_F; idx += NTHR) {
        int k = idx >> 4, c = idx & 15;
        int col = (c & 3) * HH + n0 + (c >> 2);
        sh_w2[idx] = (k < HH) ? k1[k*2048 + col] : r1[(k-HH)*2048 + col];
    }
    sh_wp[tid] = Wm[tid*DD + dcol];
    if (tid < 16) {
        int col = (tid & 3) * HH + n0 + (tid >> 2);
        sh_b0[tid] = b0[col];
        sh_b1[tid] = b1[col];
    }
    sh_c1[tid] = 0.f;
    sh_c2[tid] = 0.f;
    g_h1[0][bid*HH + tid] = 0.f;
    g_h2[0][bid*HH + tid] = 0.f;
    const float biasd = bias[dcol];
    grid_barrier();

    // ---------------- time loop ----------------
    for (int t = 0; t < TT; t++) {
        const int rb = t & 1;
        const int wb = rb ^ 1;

        // ---- Phase A: pred (-> output) + imputed cur ----
        {
            const int r  = ((bid & 1) * 64) + (tid >> 3);
            const int l8 = tid & 7;
            if (t == 0) {
                if (l8 == 0) g_cur[r*DD + dcol] = x[(r*TT)*DD + dcol];
            } else {
                const float* hrow = &g_h2[rb][r*HH + l8*64];
                const float* wv = sh_wp + l8*64;
                float sacc = 0.f;
                #pragma unroll
                for (int kk = 0; kk < 64; kk += 4) {
                    float4 h4 = *(const float4*)(hrow + kk);
                    sacc += h4.x*wv[kk] + h4.y*wv[kk+1] + h4.z*wv[kk+2] + h4.w*wv[kk+3];
                }
                sacc += __shfl_xor_sync(0xffffffffu, sacc, 4);
                sacc += __shfl_xor_sync(0xffffffffu, sacc, 2);
                sacc += __shfl_xor_sync(0xffffffffu, sacc, 1);
                if (l8 == 0) {
                    float p  = sacc + biasd;
                    float xv = x[(r*TT + t)*DD + dcol];
                    g_cur[r*DD + dcol] = (xv == 128.0f) ? p : xv;
                    out[(r*(TT-1) + (t-1))*DD + dcol] = p;
                }
            }
        }
        grid_barrier();

        // ---- Phase B: z = [cur | h1_old] @ W1 -> gates -> h1_new ----
        {
            unsigned long long acc[16] = {0,0,0,0,0,0,0,0,0,0,0,0,0,0,0,0};
            float4 pf[4];
            stage_ldg(pf, g_cur, DD, 0, tid);
            stage_sts(tA, pf, tid);
            __syncthreads();
            #pragma unroll 1
            for (int c = 0; c < 9; c++) {
                if (c + 1 < 9) stage_ldg(pf, g_h1[rb], HH, c*64, tid);
                compute_chunk(acc, (c & 1) ? tB : tA, sh_w1 + c*64*16, s, rp);
                if (c + 1 < 9) stage_sts((c & 1) ? tA : tB, pf, tid);
                __syncthreads();
            }
            write_partials(sh_red, acc, s, rp);
            __syncthreads();
            {
                const int r = tid >> 2, j = tid & 3;
                float z[4];
                #pragma unroll
                for (int g = 0; g < 4; g++) {
                    int c16 = j*4 + g;
                    float sum = sh_b0[c16];
                    #pragma unroll
                    for (int ss = 0; ss < 8; ss++)
                        sum += sh_red[ss*(128*RED_STRIDE) + r*RED_STRIDE + c16];
                    z[g] = sum;
                }
                float ig = 1.f/(1.f + expf(-z[0]));
                float fg = 1.f/(1.f + expf(-z[1]));
                float gg = tanhf(z[2]);
                float og = 1.f/(1.f + expf(-z[3]));
                float cn = fg*sh_c1[tid] + ig*gg;
                sh_c1[tid] = cn;
                g_h1[wb][r*HH + n0 + j] = og*tanhf(cn);
            }
        }
        grid_barrier();

        // ---- Phase C: z = [h1_new | h2_old] @ W2 -> gates -> h2_new ----
        {
            unsigned long long acc[16] = {0,0,0,0,0,0,0,0,0,0,0,0,0,0,0,0};
            float4 pf[4];
            stage_ldg(pf, g_h1[wb], HH, 0, tid);
            stage_sts(tA, pf, tid);
            __syncthreads();
            #pragma unroll 1
            for (int c = 0; c < 16; c++) {
                if (c + 1 < 16) {
                    const float* src = (c + 1 < 8) ? g_h1[wb] : g_h2[rb];
                    int kofs = (c + 1 < 8) ? (c+1)*64 : (c+1-8)*64;
                    stage_ldg(pf, src, HH, kofs, tid);
                }
                compute_chunk(acc, (c & 1) ? tB : tA, sh_w2 + c*64*16, s, rp);
                if (c + 1 < 16) stage_sts((c & 1) ? tA : tB, pf, tid);
                __syncthreads();
            }
            write_partials(sh_red, acc, s, rp);
            __syncthreads();
            {
                const int r = tid >> 2, j = tid & 3;
                float z[4];
                #pragma unroll
                for (int g = 0; g < 4; g++) {
                    int c16 = j*4 + g;
                    float sum = sh_b1[c16];
                    #pragma unroll
                    for (int ss = 0; ss < 8; ss++)
                        sum += sh_red[ss*(128*RED_STRIDE) + r*RED_STRIDE + c16];
                    z[g] = sum;
                }
                float ig = 1.f/(1.f + expf(-z[0]));
                float fg = 1.f/(1.f + expf(-z[1]));
                float gg = tanhf(z[2]);
                float og = 1.f/(1.f + expf(-z[3]));
                float cn = fg*sh_c2[tid] + ig*gg;
                sh_c2[tid] = cn;
                float hn = og*tanhf(cn);
                g_h2[wb][r*HH + n0 + j] = hn;
                if (t == TT-1) out[PRED_SZ + r*HH + n0 + j] = hn;
            }
        }
        grid_barrier();
    }
}

extern "C" void kernel_launch(void* const* d_in, const int* in_sizes, int n_in,
                              void* d_out, int out_size) {
    (void)in_sizes; (void)n_in; (void)out_size;
    const float* x    = (const float*)d_in[0];
    const float* k0   = (const float*)d_in[1];
    const float* r0   = (const float*)d_in[2];
    const float* b0   = (const float*)d_in[3];
    const float* k1   = (const float*)d_in[4];
    const float* r1   = (const float*)d_in[5];
    const float* b1   = (const float*)d_in[6];
    const float* Wm   = (const float*)d_in[7];
    const float* bias = (const float*)d_in[8];
    size_t smem = SMEM_FLOATS * sizeof(float);
    cudaFuncSetAttribute(ajrnn_kernel, cudaFuncAttributeMaxDynamicSharedMemorySize, (int)smem);
    ajrnn_kernel<<<NBLK, NTHR, smem>>>(x, k0, r0, b0, k1, r1, b1, Wm, bias, (float*)d_out);
}

// round 6
// speedup vs baseline: 1.6635x; 1.3148x over previous
#include <cuda_runtime.h>
#include <cuda_bf16.h>
#include <cstdint>

#define BB 128
#define TT 256
#define DD 64
#define HH 512
#define NBLK 128
#define NTHR 512
#define PRED_SZ (BB*(TT-1)*DD)

// smem byte layout
#define SM_A0HI 0
#define SM_A0LO 16384
#define SM_A1HI 32768
#define SM_A1LO 49152
#define W1_STRIDE 584                       // 576 k + 8 pad (elems)
#define W2_STRIDE 1032                      // 1024 k + 8 pad
#define SM_W1HI 65536
#define SM_W1LO (SM_W1HI + 16*W1_STRIDE*2)  // 84224
#define SM_W2HI (SM_W1LO + 16*W1_STRIDE*2)  // 102912
#define SM_W2LO (SM_W2HI + 16*W2_STRIDE*2)  // 135936
#define SM_WP   (SM_W2LO + 16*W2_STRIDE*2)  // 168960
#define SM_TOTAL (SM_WP + 2048)             // 171008

__device__ float g_h1[2][BB*HH];
__device__ float g_h2[2][BB*HH];
__device__ float g_cur[BB*DD];
__device__ unsigned int g_bar;

__device__ __forceinline__ uint32_t smem_u32(const void* p) {
    uint32_t a;
    asm("{ .reg .u64 t; cvta.to.shared.u64 t, %1; cvt.u32.u64 %0, t; }" : "=r"(a) : "l"(p));
    return a;
}
__device__ __forceinline__ uint32_t cvt2(float lo, float hi) {
    uint32_t r; asm("cvt.rn.satfinite.bf16x2.f32 %0, %1, %2;" : "=r"(r) : "f"(hi), "f"(lo)); return r;
}
__device__ __forceinline__ void ldsm4(uint32_t r[4], uint32_t addr) {
    asm volatile("ldmatrix.sync.aligned.m8n8.x4.shared.b16 {%0,%1,%2,%3}, [%4];"
        : "=r"(r[0]), "=r"(r[1]), "=r"(r[2]), "=r"(r[3]) : "r"(addr));
}
__device__ __forceinline__ void mma_bf16(float c[4], const uint32_t a[4], uint32_t b0, uint32_t b1) {
    asm volatile("mma.sync.aligned.m16n8k16.row.col.f32.bf16.bf16.f32 "
        "{%0,%1,%2,%3}, {%4,%5,%6,%7}, {%8,%9}, {%0,%1,%2,%3};"
        : "+f"(c[0]), "+f"(c[1]), "+f"(c[2]), "+f"(c[3])
        : "r"(a[0]), "r"(a[1]), "r"(a[2]), "r"(a[3]), "r"(b0), "r"(b1));
}

__device__ __forceinline__ void grid_barrier() {
    __syncthreads();
    if (threadIdx.x == 0) {
        __threadfence();
        unsigned my = atomicAdd(&g_bar, 1u) + 1u;
        unsigned target = my + (NBLK - 1u) - ((my - 1u) % NBLK);
        while ((int)(*(volatile unsigned*)&g_bar - target) < 0) __nanosleep(32);
        __threadfence();
    }
    __syncthreads();
}

// Stage [128r x 64k] fp32 -> bf16 hi/lo A tiles, ldmatrix swizzle:
// A(r,k) at byte r*128 + (((k>>3) ^ (r&7))<<4) + (k&7)*2
__device__ __forceinline__ void stage_chunk(char* bhi, char* blo, const float* __restrict__ src,
                                            int stride, int stid) {
    #pragma unroll
    for (int q = 0; q < 8; q++) {
        int lin = q*256 + stid;
        int r = lin >> 4, f4 = lin & 15;
        float4 v = *(const float4*)(src + r*stride + f4*4);
        uint32_t h01 = cvt2(v.x, v.y);
        uint32_t h23 = cvt2(v.z, v.w);
        float bx = __uint_as_float(h01 << 16), by = __uint_as_float(h01 & 0xffff0000u);
        float bz = __uint_as_float(h23 << 16), bw = __uint_as_float(h23 & 0xffff0000u);
        uint32_t l01 = cvt2(v.x - bx, v.y - by);
        uint32_t l23 = cvt2(v.z - bz, v.w - bw);
        int u = f4 >> 1;
        uint32_t off = (uint32_t)(r*128 + ((u ^ (r & 7)) << 4) + (f4 & 1)*8);
        *(uint2*)(bhi + off) = make_uint2(h01, h23);
        *(uint2*)(blo + off) = make_uint2(l01, l23);
    }
}

// One 64-k chunk of MMAs. bhi/blo already offset to chunk (= base + lane_off + c*128).
__device__ __forceinline__ void mma_chunk(float C0[4], float C1[4],
    uint32_t a_hi, uint32_t a_lo, int rsw, int ahalf, uint32_t bhi, uint32_t blo) {
    #pragma unroll
    for (int kk = 0; kk < 4; kk++) {
        uint32_t asw = (uint32_t)(((2*kk + ahalf) ^ rsw) << 4);
        uint32_t ah[4], al[4], bh[4], bl[4];
        ldsm4(ah, a_hi + asw);
        ldsm4(al, a_lo + asw);
        ldsm4(bh, bhi + kk*32);
        ldsm4(bl, blo + kk*32);
        mma_bf16(C0, ah, bh[0], bh[1]);
        mma_bf16(C1, ah, bh[2], bh[3]);
        mma_bf16(C0, ah, bl[0], bl[1]);
        mma_bf16(C1, ah, bl[2], bl[3]);
        mma_bf16(C0, al, bh[0], bh[1]);
        mma_bf16(C1, al, bh[2], bh[3]);
    }
}

__device__ __forceinline__ void gates2(const float C0[4], const float C1[4],
    float bi, float bf_, float bg, float bo, float cst[2], float hout[2]) {
    #pragma unroll
    for (int h = 0; h < 2; h++) {
        float zi = C0[2*h] + bi, zf = C0[2*h+1] + bf_;
        float zg = C1[2*h] + bg, zo = C1[2*h+1] + bo;
        float ig = 1.f/(1.f + expf(-zi));
        float fg = 1.f/(1.f + expf(-zf));
        float gg = tanhf(zg);
        float og = 1.f/(1.f + expf(-zo));
        float cn = fg*cst[h] + ig*gg;
        cst[h] = cn;
        hout[h] = og*tanhf(cn);
    }
}

__global__ void __launch_bounds__(NTHR, 1) ajrnn_kernel(
    const float* __restrict__ x,
    const float* __restrict__ k0, const float* __restrict__ r0, const float* __restrict__ b0,
    const float* __restrict__ k1, const float* __restrict__ r1, const float* __restrict__ b1,
    const float* __restrict__ Wm, const float* __restrict__ bias,
    float* __restrict__ out)
{
    extern __shared__ char smem[];
    const uint32_t smb = smem_u32(smem);
    const int tid = threadIdx.x;
    const int bid = blockIdx.x;
    const int n0  = bid * 4;
    const int dcol = bid >> 1;
    const int wid = tid >> 5, lane = tid & 31;
    float* sh_wp = (float*)(smem + SM_WP);

    // ---- weights: fp32 -> bf16 hi/lo, gate-interleaved col order ----
    // phys col p: j = (p&7)>>1 ; gate = 2*(p>>3) + (p&1) ; logical col = gate*HH + n0 + j
    unsigned short* w1h = (unsigned short*)(smem + SM_W1HI);
    unsigned short* w1l = (unsigned short*)(smem + SM_W1LO);
    unsigned short* w2h = (unsigned short*)(smem + SM_W2HI);
    unsigned short* w2l = (unsigned short*)(smem + SM_W2LO);
    for (int idx = tid; idx < 16*576; idx += NTHR) {
        int p = idx & 15, k = idx >> 4;
        int col = (2*(p>>3) + (p&1))*HH + n0 + ((p&7)>>1);
        float w = (k < DD) ? k0[k*2048 + col] : r0[(k-DD)*2048 + col];
        __nv_bfloat16 hb = __float2bfloat16(w);
        __nv_bfloat16 lb = __float2bfloat16(w - __bfloat162float(hb));
        w1h[p*W1_STRIDE + k] = __bfloat16_as_ushort(hb);
        w1l[p*W1_STRIDE + k] = __bfloat16_as_ushort(lb);
    }
    for (int idx = tid; idx < 16*1024; idx += NTHR) {
        int p = idx & 15, k = idx >> 4;
        int col = (2*(p>>3) + (p&1))*HH + n0 + ((p&7)>>1);
        float w = (k < HH) ? k1[k*2048 + col] : r1[(k-HH)*2048 + col];
        __nv_bfloat16 hb = __float2bfloat16(w);
        __nv_bfloat16 lb = __float2bfloat16(w - __bfloat162float(hb));
        w2h[p*W2_STRIDE + k] = __bfloat16_as_ushort(hb);
        w2l[p*W2_STRIDE + k] = __bfloat16_as_ushort(lb);
    }
    sh_wp[tid] = Wm[tid*DD + dcol];
    g_h1[0][bid*HH + tid] = 0.f;
    g_h2[0][bid*HH + tid] = 0.f;
    const float biasd = bias[dcol];

    // per-thread bias regs (used by compute warps)
    const int jj = lane & 3;
    const float bi0 = b0[0*HH + n0 + jj], bf0 = b0[1*HH + n0 + jj];
    const float bg0 = b0[2*HH + n0 + jj], bo0 = b0[3*HH + n0 + jj];
    const float bi1 = b1[0*HH + n0 + jj], bf1 = b1[1*HH + n0 + jj];
    const float bg1 = b1[2*HH + n0 + jj], bo1 = b1[3*HH + n0 + jj];

    // compute-warp addressing
    const int arow  = ((wid & 7) << 4) + (lane & 15);     // ldmatrix A row
    const int rsw   = arow & 7;
    const int ahalf = lane >> 4;
    const uint32_t a_row_off = (uint32_t)(arow * 128);
    const int bn  = (lane & 7) | ((lane >> 1) & 8);
    const int bk8 = (lane >> 3) & 1;
    const uint32_t b1h = smb + SM_W1HI + bn*(W1_STRIDE*2) + bk8*16;
    const uint32_t b1lo = smb + SM_W1LO + bn*(W1_STRIDE*2) + bk8*16;
    const uint32_t b2h = smb + SM_W2HI + bn*(W2_STRIDE*2) + bk8*16;
    const uint32_t b2lo = smb + SM_W2LO + bn*(W2_STRIDE*2) + bk8*16;
    const int crow = ((wid & 7) << 4) + (lane >> 2);      // C fragment row (r0; r1 = +8)
    const bool producer = (wid >= 8);
    const int stid = tid & 255;

    float c1st[2] = {0.f, 0.f}, c2st[2] = {0.f, 0.f};
    grid_barrier();

    // ---------------- time loop ----------------
    for (int t = 0; t < TT; t++) {
        const int rb = t & 1;
        const int wb = rb ^ 1;

        // ---- Phase A: pred (-> out) + imputed cur ----
        {
            const int r  = ((bid & 1) * 64) + (tid >> 3);
            const int l8 = tid & 7;
            if (t == 0) {
                if (l8 == 0) g_cur[r*DD + dcol] = x[(r*TT)*DD + dcol];
            } else {
                const float* hrow = &g_h2[rb][r*HH + l8*64];
                const float* wv = sh_wp + l8*64;
                float sacc = 0.f;
                #pragma unroll
                for (int kk = 0; kk < 64; kk += 4) {
                    float4 h4 = *(const float4*)(hrow + kk);
                    sacc += h4.x*wv[kk] + h4.y*wv[kk+1] + h4.z*wv[kk+2] + h4.w*wv[kk+3];
                }
                sacc += __shfl_xor_sync(0xffffffffu, sacc, 4);
                sacc += __shfl_xor_sync(0xffffffffu, sacc, 2);
                sacc += __shfl_xor_sync(0xffffffffu, sacc, 1);
                if (l8 == 0) {
                    float p  = sacc + biasd;
                    float xv = x[(r*TT + t)*DD + dcol];
                    g_cur[r*DD + dcol] = (xv == 128.0f) ? p : xv;
                    out[(r*(TT-1) + (t-1))*DD + dcol] = p;
                }
            }
        }
        grid_barrier();

        // ---- Phase B: z = [cur | h1_old] @ W1, 9 chunks ----
        {
            float C0[4] = {0,0,0,0}, C1[4] = {0,0,0,0};
            if (producer) stage_chunk(smem + SM_A0HI, smem + SM_A0LO, g_cur, DD, stid);
            __syncthreads();
            #pragma unroll 1
            for (int c = 0; c < 9; c++) {
                if (producer) {
                    if (c + 1 < 9) {
                        char* th = smem + (((c+1)&1) ? SM_A1HI : SM_A0HI);
                        char* tl = smem + (((c+1)&1) ? SM_A1LO : SM_A0LO);
                        stage_chunk(th, tl, g_h1[rb] + c*64, HH, stid);
                    }
                } else {
                    uint32_t ah = smb + ((c&1) ? SM_A1HI : SM_A0HI) + a_row_off;
                    uint32_t al = smb + ((c&1) ? SM_A1LO : SM_A0LO) + a_row_off;
                    mma_chunk(C0, C1, ah, al, rsw, ahalf, b1h + c*128, b1lo + c*128);
                }
                __syncthreads();
            }
            if (!producer) {
                float hout[2];
                gates2(C0, C1, bi0, bf0, bg0, bo0, c1st, hout);
                g_h1[wb][crow*HH + n0 + jj]     = hout[0];
                g_h1[wb][(crow+8)*HH + n0 + jj] = hout[1];
            }
        }
        grid_barrier();

        // ---- Phase C: z = [h1_new | h2_old] @ W2, 16 chunks ----
        {
            float C0[4] = {0,0,0,0}, C1[4] = {0,0,0,0};
            if (producer) stage_chunk(smem + SM_A0HI, smem + SM_A0LO, g_h1[wb], HH, stid);
            __syncthreads();
            #pragma unroll 1
            for (int c = 0; c < 16; c++) {
                if (producer) {
                    if (c + 1 < 16) {
                        int cc = c + 1;
                        const float* src = (cc < 8) ? (g_h1[wb] + cc*64) : (g_h2[rb] + (cc-8)*64);
                        char* th = smem + ((cc&1) ? SM_A1HI : SM_A0HI);
                        char* tl = smem + ((cc&1) ? SM_A1LO : SM_A0LO);
                        stage_chunk(th, tl, src, HH, stid);
                    }
                } else {
                    uint32_t ah = smb + ((c&1) ? SM_A1HI : SM_A0HI) + a_row_off;
                    uint32_t al = smb + ((c&1) ? SM_A1LO : SM_A0LO) + a_row_off;
                    mma_chunk(C0, C1, ah, al, rsw, ahalf, b2h + c*128, b2lo + c*128);
                }
                __syncthreads();
            }
            if (!producer) {
                float hout[2];
                gates2(C0, C1, bi1, bf1, bg1, bo1, c2st, hout);
                g_h2[wb][crow*HH + n0 + jj]     = hout[0];
                g_h2[wb][(crow+8)*HH + n0 + jj] = hout[1];
                if (t == TT-1) {
                    out[PRED_SZ + crow*HH + n0 + jj]     = hout[0];
                    out[PRED_SZ + (crow+8)*HH + n0 + jj] = hout[1];
                }
            }
        }
        grid_barrier();
    }
}

extern "C" void kernel_launch(void* const* d_in, const int* in_sizes, int n_in,
                              void* d_out, int out_size) {
    (void)in_sizes; (void)n_in; (void)out_size;
    const float* x    = (const float*)d_in[0];
    const float* k0   = (const float*)d_in[1];
    const float* r0   = (const float*)d_in[2];
    const float* b0   = (const float*)d_in[3];
    const float* k1   = (const float*)d_in[4];
    const float* r1   = (const float*)d_in[5];
    const float* b1   = (const float*)d_in[6];
    const float* Wm   = (const float*)d_in[7];
    const float* bias = (const float*)d_in[8];
    cudaFuncSetAttribute(ajrnn_kernel, cudaFuncAttributeMaxDynamicSharedMemorySize, SM_TOTAL);
    ajrnn_kernel<<<NBLK, NTHR, SM_TOTAL>>>(x, k0, r0, b0, k1, r1, b1, Wm, bias, (float*)d_out);
}